// round 9
// baseline (speedup 1.0000x reference)
#include <cuda_runtime.h>
#include <cstddef>
#include <cstdint>

// CTC loss forward, fused single-kernel. B=32, T=800, C=5000, L=100, S=201.
//
// R8 vs R7 (145us; R6 127.7us):
//  * asm-volatile ordering pins REVERTED (they serialized the loop; ptxas
//    scheduling freedom wins).
//  * Lagged-halo warp tiling: the recurrence moves left->right <=2 states per
//    step, so each warp runs 8 steps independently with an 8-lane redundant
//    left halo. Neighbor exchange inside a window is __shfl_up_sync (no
//    LDS/STS, no block barrier). One __syncthreads per 8 steps (publish
//    output lanes / reload halo lanes via double-buffered smem).
//  * 5 warps x 32 lanes x 2 states; warp w lane l owns slot 24w-8+l.
//    Lanes 0-7 halo, lanes 8-31 output -> 120 output slots >= 101.
//  * 3 ex2/step (cascaded single-ex2 logaddexp); own-odd(+)own-even combine
//    overlaps the shfl latency.
//  * reduce fused into alpha via threadfence-reduction last-block pattern.

#define Bb 32
#define Tt 800
#define Cc 5000
#define Ll 100
#define NEGV (-1e30f)
#define LOG2E 1.4426950408889634f
#define LN2   0.6931471805599453f
#define W 8               // window length == halo lanes == prefetch depth
#define NWARP 5
#define NTHR (NWARP * 32)

__device__ float    g_tot[Bb];
__device__ unsigned g_done;      // zero-init; reset by the finishing block

__device__ __forceinline__ float ex2f(float x) {
    float y; asm("ex2.approx.ftz.f32 %0, %1;" : "=f"(y) : "f"(x)); return y;
}
__device__ __forceinline__ float lg2f(float x) {
    float y; asm("lg2.approx.ftz.f32 %0, %1;" : "=f"(y) : "f"(x)); return y;
}

// ---------------------------------------------------------------------------
// Fused gather + alpha + final reduction. grid = B blocks, 160 threads.
// ---------------------------------------------------------------------------
__global__ __launch_bounds__(NTHR, 1)
void ctc_alpha_fused(const float* __restrict__ lp,
                     const int* __restrict__ targets,
                     const int* __restrict__ ilen,
                     const int* __restrict__ tlen,
                     float* __restrict__ out)
{
    // pub[buf][slot+8] = (be,se,bo,so). Indices 0..7 are permanent NEG pads
    // (left boundary for warp 0's halo).
    __shared__ float4 pub[2][136];
    __shared__ int s_last;

    const int b   = blockIdx.x;
    const int tid = threadIdx.x;
    const int w   = tid >> 5;
    const int l   = tid & 31;
    const int slot = 24 * w - 8 + l;          // -8 .. 111
    const int last = ilen[b] - 1;             // >= 599 here

    const int  tg   = (slot >= 0 && slot < Ll) ? targets[b * Ll + slot] : 0;
    const int  tgp  = (slot >= 1 && slot <= Ll) ? targets[b * Ll + slot - 1] : -1;
    const bool skip = (tg != tgp);
    const float* __restrict__ rowb = lp + (size_t)b * Tt * Cc;

    if (tid < W) {
        pub[0][tid] = make_float4(NEGV, 0.f, NEGV, 0.f);
        pub[1][tid] = make_float4(NEGV, 0.f, NEGV, 0.f);
    }

    // t=0 init (log2 domain, alpha = base + lg2(sum)): states 0,1 live.
    float se = 1.f, so = 1.f;
    float be = (slot == 0) ? LOG2E * rowb[0]  : NEGV;
    float bo = (slot == 0) ? LOG2E * rowb[tg] : NEGV;

    // Depth-8 prefetch rings: blank col 0 (broadcast) + own target col.
    float eb[W], eo[W];
#pragma unroll
    for (int k = 0; k < W; ++k) {
        int tt = 1 + k; if (tt > last) tt = last;
        const float* p = rowb + (size_t)tt * Cc;
        eb[k] = p[0];
        eo[k] = __ldg(p + tg);
    }
    __syncthreads();

    int buf = 0;
    int t = 1;
    while (t <= last) {
#pragma unroll
        for (int u = 0; u < W; ++u) {
            if (t + u <= last) {
                // neighbor's odd (base,sum) from previous step; lane 0
                // self-clamps (wrong but contained inside the halo).
                float nbz = __shfl_up_sync(0xffffffffu, bo, 1);
                float nbw = __shfl_up_sync(0xffffffffu, so, 1);

                float ecb = LOG2E * eb[u];
                float eco = LOG2E * eo[u];
                int tp = t + u + W; if (tp > last) tp = last;
                const float* p = rowb + (size_t)tp * Cc;
                float neb = p[0];
                float neo = __ldg(p + tg);

                // own odd (+) own even -- no neighbor data; overlaps shfl.
                float d1 = bo - be;
                float t1 = ex2f(fminf(d1, -d1));
                float m1 = fmaxf(bo, be);
                float s1 = (d1 >= 0.f) ? fmaf(se, t1, so) : fmaf(so, t1, se);
                // even state: self (+) neighbor odd.
                float d0 = be - nbz;
                float t0 = ex2f(fminf(d0, -d0));
                float me = fmaxf(be, nbz);
                float te = (d0 >= 0.f) ? fmaf(nbw, t0, se) : fmaf(se, t0, nbw);
                // odd state: (own pair) (+) neighbor odd if skip-arc.
                float bz2 = skip ? nbz : NEGV;
                float w2  = skip ? nbw : 0.f;
                float d2 = m1 - bz2;
                float t2 = ex2f(fminf(d2, -d2));
                float mo = fmaxf(m1, bz2);
                float s2 = (d2 >= 0.f) ? fmaf(w2, t2, s1) : fmaf(s1, t2, w2);

                be = me + ecb; se = te;
                bo = mo + eco; so = s2;
                eb[u] = neb; eo[u] = neo;
            }
        }
        t += W;
        if (t <= last) {                      // window boundary
            be = fmaxf(be + lg2f(se), NEGV); se = 1.f;
            bo = fmaxf(bo + lg2f(so), NEGV); so = 1.f;
            buf ^= 1;
            if (l >= W) pub[buf][slot + 8] = make_float4(be, se, bo, so);
            __syncthreads();
            if (l < W) {
                float4 v = pub[buf][slot + 8];
                be = v.x; se = v.y; bo = v.z; so = v.w;
            }
        }
    }

    // Final fold + publish output lanes, then score + fused reduction.
    be = fmaxf(be + lg2f(se), NEGV);
    bo = fmaxf(bo + lg2f(so), NEGV);
    buf ^= 1;
    if (l >= W) pub[buf][slot + 8] = make_float4(be, 1.f, bo, 1.f);
    __syncthreads();

    if (tid == 0) {
        int Lb = tlen[b];
        float x = pub[buf][Lb + 8].x;         // even state 2Lb   (slot Lb)
        float y = pub[buf][Lb - 1 + 8].z;     // odd  state 2Lb-1 (slot Lb-1)
        float m = fmaxf(x, y);
        g_tot[b] = LN2 * (m + lg2f(ex2f(x - m) + ex2f(y - m)));
        __threadfence();
        unsigned v = atomicAdd(&g_done, 1u);
        s_last = (v == Bb - 1u) ? 1 : 0;
    }
    __syncthreads();

    if (s_last && tid < 32) {                 // last block reduces (warp 0)
        __threadfence();
        float tot = g_tot[tid];
        float il  = (float)ilen[tid];
        bool  ok  = tot > NEGV * 0.5f;
        float ts = ok ? tot : 0.f;
        float tf = ok ? il  : 0.f;
        float af = il;
#pragma unroll
        for (int s = 16; s >= 1; s >>= 1) {
            ts += __shfl_down_sync(0xFFFFFFFFu, ts, s);
            tf += __shfl_down_sync(0xFFFFFFFFu, tf, s);
            af += __shfl_down_sync(0xFFFFFFFFu, af, s);
        }
        if (tid == 0) {
            out[0] = ts; out[1] = tf; out[2] = af;
            g_done = 0;                       // reset for next graph replay
        }
    }
}

// ---------------------------------------------------------------------------
extern "C" void kernel_launch(void* const* d_in, const int* in_sizes, int n_in,
                              void* d_out, int out_size) {
    const float* lp      = (const float*)d_in[0];  // nnet_output [B,T,C] f32
    const int*   targets = (const int*)  d_in[1];  // [B,L] i32
    const int*   ilen    = (const int*)  d_in[2];  // [B] i32
    const int*   tlen    = (const int*)  d_in[3];  // [B] i32

    ctc_alpha_fused<<<Bb, NTHR>>>(lp, targets, ilen, tlen, (float*)d_out);
}

// round 10
// speedup vs baseline: 1.6119x; 1.6119x over previous
#include <cuda_runtime.h>
#include <cstddef>
#include <cstdint>

// CTC loss forward, fused single-kernel. B=32, T=800, C=5000, L=100, S=201.
//
// R9: back to the proven R6 skeleton (128 threads, 2 states/thread, smem
// double-buffer exchange), but TWO time steps per barrier: each thread reads
// neighbor's float4 and next-neighbor's odd pair, redundantly recomputes the
// neighbor's odd state at t+1 (extra emission col = targets[i-1], L1-resident
// from the neighbor's own load), and uses it for its own t+2 update.
// Halves barrier+LDS count per step. Reduction fused (last-block pattern).
// R8's shfl/halo structure abandoned (issue=3.9%, ~1070cyc/step: compilation
// pathology, likely local-memory rings).

#define Bb 32
#define Tt 800
#define Cc 5000
#define Ll 100
#define NEGV (-1e30f)
#define LOG2E 1.4426950408889634f
#define LN2   0.6931471805599453f
#define DP 4              // prefetch depth in PAIRS (8 time steps)
#define NTHR 128

__device__ float    g_tot[Bb];
__device__ unsigned g_done;          // zero-init; reset by finishing block

__device__ __forceinline__ float ex2f(float x) {
    float y; asm("ex2.approx.ftz.f32 %0, %1;" : "=f"(y) : "f"(x)); return y;
}
__device__ __forceinline__ float lg2f(float x) {
    float y; asm("lg2.approx.ftz.f32 %0, %1;" : "=f"(y) : "f"(x)); return y;
}

// (base,sum) logaddexp combine: (bx,sx) (+) (by,sy) -> (mb, ms), single ex2.
#define LAE(bx, sx, by, sy, mb, ms)                                        \
    {                                                                      \
        float d_ = __fadd_rn(bx, -(by));                                   \
        float u_ = ex2f(fminf(d_, -d_));                                   \
        mb = fmaxf(bx, by);                                                \
        ms = (d_ >= 0.f) ? __fmaf_rn(sy, u_, sx) : __fmaf_rn(sx, u_, sy);  \
    }

// ---------------------------------------------------------------------------
// Fused gather + alpha + reduction. grid = B blocks, 128 threads (4 warps).
// ---------------------------------------------------------------------------
__global__ __launch_bounds__(NTHR, 1)
void ctc_alpha_fused(const float* __restrict__ lp,
                     const int* __restrict__ targets,
                     const int* __restrict__ ilen,
                     const int* __restrict__ tlen,
                     float* __restrict__ out)
{
    // slot i+2 = thread i's (be,se,bo,so); slots 0,1 = permanent dead pads.
    __shared__ float4 sh[2][NTHR + 2];
    __shared__ int s_lastflag;

    const int b = blockIdx.x;
    const int i = threadIdx.x;
    const int last = ilen[b] - 1;    // >= 599 for this problem

    // Static per-thread params (sentinel -1 outside valid range).
    const int tgR   = (i < Ll)              ? targets[b * Ll + i]     : 0;
    const int tgpR  = (i >= 1 && i <= Ll)   ? targets[b * Ll + i - 1] : -1;
    const int tgppR = (i >= 2 && i <= Ll+1) ? targets[b * Ll + i - 2] : -1;
    const bool skip  = (tgR  != tgpR);   // own odd state's skip arc
    const bool skipP = (tgpR != tgppR);  // neighbor's odd state's skip arc
    const int tgo = tgR;                       // own odd emission column
    const int tgp = (tgpR >= 0) ? tgpR : 0;    // neighbor odd emission column

    const float* __restrict__ rowb = lp + (size_t)b * Tt * Cc;

    if (i < 2) {
        sh[0][i] = make_float4(NEGV, 0.f, NEGV, 0.f);
        sh[1][i] = make_float4(NEGV, 0.f, NEGV, 0.f);
    }

    // t=0 init (log2 domain, alpha = base + lg2(sum)): states 0,1 live.
    float se = 1.f, so = 1.f;
    float be = (i == 0) ? __fmul_rn(LOG2E, rowb[0])   : NEGV;
    float bo = (i == 0) ? __fmul_rn(LOG2E, rowb[tgo]) : NEGV;

    int buf = 0;
    sh[buf][i + 2] = make_float4(be, se, bo, so);
    __syncthreads();

    // If step count (last) is odd, do ONE plain step first so pairs align.
    int ts = 0;                      // current state time
    if (last & 1) {
        float4 n1 = sh[buf][i + 1];
        const float* p = rowb + (size_t)1 * Cc;
        float e_b = p[0];
        float e_o = __ldg(p + tgo);
        float mA, sA; LAE(be, se, n1.z, n1.w, mA, sA);
        float m1, s1; LAE(bo, so, be, se, m1, s1);
        float bz = skip ? n1.z : NEGV, wz = skip ? n1.w : 0.f;
        float mC, sC; LAE(m1, s1, bz, wz, mC, sC);
        be = __fadd_rn(mA, __fmul_rn(LOG2E, e_b)); se = sA;
        bo = __fadd_rn(mC, __fmul_rn(LOG2E, e_o)); so = sC;
        ts = 1;
        buf ^= 1;
        sh[buf][i + 2] = make_float4(be, se, bo, so);
        __syncthreads();
    }
    const int npairs = (last - ts) >> 1;     // exact; >= 299 here

    // Prefetch rings, depth DP pairs: per pair need emissions at tc+1
    // (blank, own-odd, neighbor-odd) and tc+2 (blank, own-odd).
    float r1b[DP], r1o[DP], r1p[DP], r2b[DP], r2o[DP];
#pragma unroll
    for (int k = 0; k < DP; ++k) {
        int q = (k < npairs) ? k : (npairs - 1);
        const float* p1 = rowb + (size_t)(ts + 2 * q + 1) * Cc;
        const float* p2 = rowb + (size_t)(ts + 2 * q + 2) * Cc;
        r1b[k] = p1[0]; r1o[k] = __ldg(p1 + tgo); r1p[k] = __ldg(p1 + tgp);
        r2b[k] = p2[0]; r2o[k] = __ldg(p2 + tgo);
    }

    for (int p = 0; p < npairs; ++p) {
        const int k = p & (DP - 1);
        const float e1b = r1b[k], e1o = r1o[k], e1p = r1p[k];
        const float e2b = r2b[k], e2o = r2o[k];
        int q = p + DP; if (q >= npairs) q = npairs - 1;
        const float* pp1 = rowb + (size_t)(ts + 2 * q + 1) * Cc;
        const float* pp2 = rowb + (size_t)(ts + 2 * q + 2) * Cc;
        r1b[k] = pp1[0]; r1o[k] = __ldg(pp1 + tgo); r1p[k] = __ldg(pp1 + tgp);
        r2b[k] = pp2[0]; r2o[k] = __ldg(pp2 + tgo);

        float4 n1 = sh[buf][i + 1];      // thread i-1's state at time tc
        float4 n2 = sh[buf][i];          // thread i-2's state at time tc

        // --- Redundant: neighbor (i-1)'s odd state at tc+1.
        // Structurally identical to the primary odd update below -> matches
        // the neighbor's own computation. Dead pads (NEG,0) flow through as
        // zero-weight terms, so i==0 needs no special case.
        float mR1, sR1; LAE(n1.z, n1.w, n1.x, n1.y, mR1, sR1);
        float bzR = skipP ? n2.z : NEGV, wzR = skipP ? n2.w : 0.f;
        float mRP, sP;  LAE(mR1, sR1, bzR, wzR, mRP, sP);
        float bP = __fadd_rn(mRP, __fmul_rn(LOG2E, e1p));

        // --- Own step tc+1.
        float mA, sA; LAE(be, se, n1.z, n1.w, mA, sA);             // even
        float m1, s1; LAE(bo, so, be, se, m1, s1);                 // odd cascade
        float bzB = skip ? n1.z : NEGV, wzB = skip ? n1.w : 0.f;
        float mC, sC; LAE(m1, s1, bzB, wzB, mC, sC);
        float be1 = __fadd_rn(mA, __fmul_rn(LOG2E, e1b)), se1 = sA;
        float bo1 = __fadd_rn(mC, __fmul_rn(LOG2E, e1o)), so1 = sC;

        // --- Own step tc+2 (neighbor odd = redundant (bP,sP)).
        float mD, sD; LAE(be1, se1, bP, sP, mD, sD);               // even
        float mE, sE; LAE(bo1, so1, be1, se1, mE, sE);             // odd cascade
        float bzF = skip ? bP : NEGV, wzF = skip ? sP : 0.f;
        float mF, sF; LAE(mE, sE, bzF, wzF, mF, sF);
        be = __fadd_rn(mD, __fmul_rn(LOG2E, e2b)); se = sD;
        bo = __fadd_rn(mF, __fmul_rn(LOG2E, e2o)); so = sF;

        if ((p & 15) == 15) {            // fold every 32 steps (3^32 < f32max)
            be = fmaxf(be + lg2f(se), NEGV); se = 1.f;
            bo = fmaxf(bo + lg2f(so), NEGV); so = 1.f;
        }

        buf ^= 1;
        sh[buf][i + 2] = make_float4(be, se, bo, so);
        __syncthreads();
    }

    // Final fold + publish (sum folded to 1 so .x/.z are full alphas).
    be = fmaxf(be + lg2f(se), NEGV);
    bo = fmaxf(bo + lg2f(so), NEGV);
    buf ^= 1;
    sh[buf][i + 2] = make_float4(be, 1.f, bo, 1.f);
    __syncthreads();

    if (i == 0) {
        int Lb = tlen[b];
        float x = sh[buf][Lb + 2].x;     // even state 2Lb   (thread Lb)
        float y = sh[buf][Lb + 1].z;     // odd  state 2Lb-1 (thread Lb-1)
        float m = fmaxf(x, y);
        g_tot[b] = LN2 * (m + lg2f(ex2f(x - m) + ex2f(y - m)));
        __threadfence();
        unsigned v = atomicAdd(&g_done, 1u);
        s_lastflag = (v == Bb - 1u) ? 1 : 0;
    }
    __syncthreads();

    if (s_lastflag && i < 32) {          // last block: fused reduction
        __threadfence();
        float tot = g_tot[i];
        float il  = (float)ilen[i];
        bool  ok  = tot > NEGV * 0.5f;
        float tsum = ok ? tot : 0.f;
        float tf   = ok ? il  : 0.f;
        float af   = il;
#pragma unroll
        for (int s = 16; s >= 1; s >>= 1) {
            tsum += __shfl_down_sync(0xFFFFFFFFu, tsum, s);
            tf   += __shfl_down_sync(0xFFFFFFFFu, tf, s);
            af   += __shfl_down_sync(0xFFFFFFFFu, af, s);
        }
        if (i == 0) {
            out[0] = tsum; out[1] = tf; out[2] = af;
            g_done = 0;                  // reset for next graph replay
        }
    }
}

// ---------------------------------------------------------------------------
extern "C" void kernel_launch(void* const* d_in, const int* in_sizes, int n_in,
                              void* d_out, int out_size) {
    const float* lp      = (const float*)d_in[0];  // nnet_output [B,T,C] f32
    const int*   targets = (const int*)  d_in[1];  // [B,L] i32
    const int*   ilen    = (const int*)  d_in[2];  // [B] i32
    const int*   tlen    = (const int*)  d_in[3];  // [B] i32

    ctc_alpha_fused<<<Bb, NTHR>>>(lp, targets, ilen, tlen, (float*)d_out);
}

// round 11
// speedup vs baseline: 3.9300x; 2.4381x over previous
#include <cuda_runtime.h>
#include <cstddef>
#include <cstdint>

// CTC loss forward, fused single-kernel. B=32, T=800, C=5000, L=100, S=201.
//
// R10 = R9 (two time steps per barrier via redundant neighbor-odd recompute)
// with the local-memory bug fixed: R9's pair loop had NO unroll pragma, so
// ring index k = p&3 was dynamic -> rings spilled to local memory (STL/LDL on
// every step; 306us). R8 failed the same way. Fix: grouped outer loop +
// fully-unrolled inner loop with LITERAL ring indices; <=3 remainder pairs in
// a ring-free epilogue.

#define Bb 32
#define Tt 800
#define Cc 5000
#define Ll 100
#define NEGV (-1e30f)
#define LOG2E 1.4426950408889634f
#define LN2   0.6931471805599453f
#define DP 4              // prefetch depth in PAIRS (8 time steps)
#define NTHR 128

__device__ float    g_tot[Bb];
__device__ unsigned g_done;          // zero-init; reset by finishing block

__device__ __forceinline__ float ex2f(float x) {
    float y; asm("ex2.approx.ftz.f32 %0, %1;" : "=f"(y) : "f"(x)); return y;
}
__device__ __forceinline__ float lg2f(float x) {
    float y; asm("lg2.approx.ftz.f32 %0, %1;" : "=f"(y) : "f"(x)); return y;
}

// (base,sum) logaddexp combine: (bx,sx) (+) (by,sy) -> (mb, ms), single ex2.
#define LAE(bx, sx, by, sy, mb, ms)                                        \
    {                                                                      \
        float d_ = __fadd_rn(bx, -(by));                                   \
        float u_ = ex2f(fminf(d_, -d_));                                   \
        mb = fmaxf(bx, by);                                                \
        ms = (d_ >= 0.f) ? __fmaf_rn(sy, u_, sx) : __fmaf_rn(sx, u_, sy);  \
    }

// ---------------------------------------------------------------------------
// Fused gather + alpha + reduction. grid = B blocks, 128 threads (4 warps).
// ---------------------------------------------------------------------------
__global__ __launch_bounds__(NTHR, 1)
void ctc_alpha_fused(const float* __restrict__ lp,
                     const int* __restrict__ targets,
                     const int* __restrict__ ilen,
                     const int* __restrict__ tlen,
                     float* __restrict__ out)
{
    // slot i+2 = thread i's (be,se,bo,so); slots 0,1 = permanent dead pads.
    __shared__ float4 sh[2][NTHR + 2];
    __shared__ int s_lastflag;

    const int b = blockIdx.x;
    const int i = threadIdx.x;
    const int last = ilen[b] - 1;    // >= 599 for this problem

    const int tgR   = (i < Ll)              ? targets[b * Ll + i]     : 0;
    const int tgpR  = (i >= 1 && i <= Ll)   ? targets[b * Ll + i - 1] : -1;
    const int tgppR = (i >= 2 && i <= Ll+1) ? targets[b * Ll + i - 2] : -1;
    const bool skip  = (tgR  != tgpR);   // own odd state's skip arc
    const bool skipP = (tgpR != tgppR);  // neighbor's odd state's skip arc
    const int tgo = tgR;                       // own odd emission column
    const int tgp = (tgpR >= 0) ? tgpR : 0;    // neighbor odd emission column

    const float* __restrict__ rowb = lp + (size_t)b * Tt * Cc;

    if (i < 2) {
        sh[0][i] = make_float4(NEGV, 0.f, NEGV, 0.f);
        sh[1][i] = make_float4(NEGV, 0.f, NEGV, 0.f);
    }

    // t=0 init (log2 domain, alpha = base + lg2(sum)): states 0,1 live.
    float se = 1.f, so = 1.f;
    float be = (i == 0) ? __fmul_rn(LOG2E, rowb[0])   : NEGV;
    float bo = (i == 0) ? __fmul_rn(LOG2E, rowb[tgo]) : NEGV;

    int buf = 0;
    sh[buf][i + 2] = make_float4(be, se, bo, so);
    __syncthreads();

    // One PAIR of steps: (tc+1, tc+2) given emissions e1*, e2*.
#define PAIR_BODY(e1b, e1o, e1p, e2b, e2o)                                   \
    {                                                                        \
        float4 n1 = sh[buf][i + 1];                                          \
        float4 n2 = sh[buf][i];                                              \
        /* redundant: neighbor (i-1)'s odd state at tc+1 */                  \
        float mR1, sR1; LAE(n1.z, n1.w, n1.x, n1.y, mR1, sR1);               \
        float bzR = skipP ? n2.z : NEGV, wzR = skipP ? n2.w : 0.f;           \
        float mRP, sP;  LAE(mR1, sR1, bzR, wzR, mRP, sP);                    \
        float bP = __fadd_rn(mRP, __fmul_rn(LOG2E, (e1p)));                  \
        /* own step tc+1 */                                                  \
        float mA, sA; LAE(be, se, n1.z, n1.w, mA, sA);                       \
        float m1, s1; LAE(bo, so, be, se, m1, s1);                           \
        float bzB = skip ? n1.z : NEGV, wzB = skip ? n1.w : 0.f;             \
        float mC, sC; LAE(m1, s1, bzB, wzB, mC, sC);                         \
        float be1 = __fadd_rn(mA, __fmul_rn(LOG2E, (e1b))), se1 = sA;        \
        float bo1 = __fadd_rn(mC, __fmul_rn(LOG2E, (e1o))), so1 = sC;        \
        /* own step tc+2 (neighbor odd = redundant (bP,sP)) */               \
        float mD, sD; LAE(be1, se1, bP, sP, mD, sD);                         \
        float mE, sE; LAE(bo1, so1, be1, se1, mE, sE);                       \
        float bzF = skip ? bP : NEGV, wzF = skip ? sP : 0.f;                 \
        float mF, sF; LAE(mE, sE, bzF, wzF, mF, sF);                         \
        be = __fadd_rn(mD, __fmul_rn(LOG2E, (e2b))); se = sD;                \
        bo = __fadd_rn(mF, __fmul_rn(LOG2E, (e2o))); so = sF;                \
    }

    // If step count (last) is odd, do ONE plain step first so pairs align.
    int ts = 0;
    if (last & 1) {
        float4 n1 = sh[buf][i + 1];
        const float* p = rowb + (size_t)Cc;
        float e_b = p[0];
        float e_o = __ldg(p + tgo);
        float mA, sA; LAE(be, se, n1.z, n1.w, mA, sA);
        float m1, s1; LAE(bo, so, be, se, m1, s1);
        float bz = skip ? n1.z : NEGV, wz = skip ? n1.w : 0.f;
        float mC, sC; LAE(m1, s1, bz, wz, mC, sC);
        be = __fadd_rn(mA, __fmul_rn(LOG2E, e_b)); se = sA;
        bo = __fadd_rn(mC, __fmul_rn(LOG2E, e_o)); so = sC;
        ts = 1;
        buf ^= 1;
        sh[buf][i + 2] = make_float4(be, se, bo, so);
        __syncthreads();
    }
    const int npairs = (last - ts) >> 1;          // >= 299 here
    const int nmain  = npairs & ~(DP - 1);        // grouped-unrolled portion

    // Register prefetch rings (indices are LITERALS everywhere below).
    float r1b[DP], r1o[DP], r1p[DP], r2b[DP], r2o[DP];
#pragma unroll
    for (int k = 0; k < DP; ++k) {
        const float* p1 = rowb + (size_t)(ts + 2 * k + 1) * Cc;
        const float* p2 = rowb + (size_t)(ts + 2 * k + 2) * Cc;
        r1b[k] = p1[0]; r1o[k] = __ldg(p1 + tgo); r1p[k] = __ldg(p1 + tgp);
        r2b[k] = p2[0]; r2o[k] = __ldg(p2 + tgo);
    }

    for (int pg = 0; pg < nmain; pg += DP) {
#pragma unroll
        for (int k = 0; k < DP; ++k) {            // k is a literal
            const int p = pg + k;
            const float e1b = r1b[k], e1o = r1o[k], e1p = r1p[k];
            const float e2b = r2b[k], e2o = r2o[k];
            // refill slot k with pair p+DP (clamped; unused slots harmless)
            int q = p + DP; if (q >= npairs) q = npairs - 1;
            const float* pp1 = rowb + (size_t)(ts + 2 * q + 1) * Cc;
            const float* pp2 = rowb + (size_t)(ts + 2 * q + 2) * Cc;
            r1b[k] = pp1[0]; r1o[k] = __ldg(pp1 + tgo); r1p[k] = __ldg(pp1 + tgp);
            r2b[k] = pp2[0]; r2o[k] = __ldg(pp2 + tgo);

            PAIR_BODY(e1b, e1o, e1p, e2b, e2o);

            if ((p & 15) == 15) {    // fold every 32 steps (3^32 < f32max)
                be = fmaxf(be + lg2f(se), NEGV); se = 1.f;
                bo = fmaxf(bo + lg2f(so), NEGV); so = 1.f;
            }
            buf ^= 1;
            sh[buf][i + 2] = make_float4(be, se, bo, so);
            __syncthreads();
        }
    }

    // Remainder pairs (<=3): ring-free, direct loads.
    for (int p = nmain; p < npairs; ++p) {
        const float* p1 = rowb + (size_t)(ts + 2 * p + 1) * Cc;
        const float* p2 = rowb + (size_t)(ts + 2 * p + 2) * Cc;
        float e1b = p1[0], e1o = __ldg(p1 + tgo), e1p = __ldg(p1 + tgp);
        float e2b = p2[0], e2o = __ldg(p2 + tgo);
        PAIR_BODY(e1b, e1o, e1p, e2b, e2o);
        buf ^= 1;
        sh[buf][i + 2] = make_float4(be, se, bo, so);
        __syncthreads();
    }

    // Final fold + publish (sum folded to 1 so .x/.z are full alphas).
    be = fmaxf(be + lg2f(se), NEGV);
    bo = fmaxf(bo + lg2f(so), NEGV);
    buf ^= 1;
    sh[buf][i + 2] = make_float4(be, 1.f, bo, 1.f);
    __syncthreads();

    if (i == 0) {
        int Lb = tlen[b];
        float x = sh[buf][Lb + 2].x;     // even state 2Lb   (thread Lb)
        float y = sh[buf][Lb + 1].z;     // odd  state 2Lb-1 (thread Lb-1)
        float m = fmaxf(x, y);
        g_tot[b] = LN2 * (m + lg2f(ex2f(x - m) + ex2f(y - m)));
        __threadfence();
        unsigned v = atomicAdd(&g_done, 1u);
        s_lastflag = (v == Bb - 1u) ? 1 : 0;
    }
    __syncthreads();

    if (s_lastflag && i < 32) {          // last block: fused reduction
        __threadfence();
        float tot = g_tot[i];
        float il  = (float)ilen[i];
        bool  ok  = tot > NEGV * 0.5f;
        float tsum = ok ? tot : 0.f;
        float tf   = ok ? il  : 0.f;
        float af   = il;
#pragma unroll
        for (int s = 16; s >= 1; s >>= 1) {
            tsum += __shfl_down_sync(0xFFFFFFFFu, tsum, s);
            tf   += __shfl_down_sync(0xFFFFFFFFu, tf, s);
            af   += __shfl_down_sync(0xFFFFFFFFu, af, s);
        }
        if (i == 0) {
            out[0] = tsum; out[1] = tf; out[2] = af;
            g_done = 0;                  // reset for next graph replay
        }
    }
}

// ---------------------------------------------------------------------------
extern "C" void kernel_launch(void* const* d_in, const int* in_sizes, int n_in,
                              void* d_out, int out_size) {
    const float* lp      = (const float*)d_in[0];  // nnet_output [B,T,C] f32
    const int*   targets = (const int*)  d_in[1];  // [B,L] i32
    const int*   ilen    = (const int*)  d_in[2];  // [B] i32
    const int*   tlen    = (const int*)  d_in[3];  // [B] i32

    ctc_alpha_fused<<<Bb, NTHR>>>(lp, targets, ilen, tlen, (float*)d_out);
}

// round 12
// speedup vs baseline: 4.1632x; 1.0593x over previous
#include <cuda_runtime.h>
#include <cstddef>
#include <cstdint>

// CTC loss forward. B=32, T=800, C=5000, L=100, S=201.
//
// R11: un-fuse the gather. R6/R10's fused design was bound by the L1tex
// wavefront queue (~86 wf/warp/pair of scattered LDGs on only 32 SMs ->
// ~80us floor; ncu showed 1.7TB/s DRAM during the recursion). Split:
//  1) gather_kernel (full chip, DRAM-bound ~40us): dense emit scratch,
//     LOG2E-prescaled, trimmed to t < ilen[b], EP=128 line-aligned rows.
//  2) ctc_alpha: R10's two-steps-per-barrier pair recursion, emissions now
//     coalesced L2 reads from emit (~8 wf/warp/pair) -> chain+barrier bound.
//     Fused last-block reduction.

#define Bb 32
#define Tt 800
#define Cc 5000
#define Ll 100
#define EP 128            // emit row stride (floats), line-aligned
#define NEGV (-1e30f)
#define LOG2E 1.4426950408889634f
#define LN2   0.6931471805599453f
#define DP 4              // prefetch depth in PAIRS (8 time steps)
#define NTHR 128

__device__ float    g_emit[(size_t)Bb * Tt * EP];
__device__ float    g_tot[Bb];
__device__ unsigned g_done;          // zero-init; reset by finishing block

__device__ __forceinline__ float ex2f(float x) {
    float y; asm("ex2.approx.ftz.f32 %0, %1;" : "=f"(y) : "f"(x)); return y;
}
__device__ __forceinline__ float lg2f(float x) {
    float y; asm("lg2.approx.ftz.f32 %0, %1;" : "=f"(y) : "f"(x)); return y;
}

// (base,sum) logaddexp combine: (bx,sx) (+) (by,sy) -> (mb, ms), single ex2.
#define LAE(bx, sx, by, sy, mb, ms)                                        \
    {                                                                      \
        float d_ = __fadd_rn(bx, -(by));                                   \
        float u_ = ex2f(fminf(d_, -d_));                                   \
        mb = fmaxf(bx, by);                                                \
        ms = (d_ >= 0.f) ? __fmaf_rn(sy, u_, sx) : __fmaf_rn(sx, u_, sy);  \
    }

// ---------------------------------------------------------------------------
// Kernel 1: gather (full chip). emit[bt][j] = LOG2E * lp[bt, col(j)],
// j = 0 (blank) or 1..L (targets). Skips t >= ilen[b].
// ---------------------------------------------------------------------------
__global__ void gather_kernel(const float* __restrict__ lp,
                              const int* __restrict__ targets,
                              const int* __restrict__ ilen) {
    int idx = blockIdx.x * blockDim.x + threadIdx.x;
    const int total = Bb * Tt * (Ll + 1);
    if (idx >= total) return;
    int j  = idx % (Ll + 1);
    int bt = idx / (Ll + 1);
    int b  = bt / Tt;
    int t  = bt - b * Tt;
    if (t >= ilen[b]) return;
    int c = (j == 0) ? 0 : targets[b * Ll + (j - 1)];
    g_emit[(size_t)bt * EP + j] = LOG2E * __ldg(lp + (size_t)bt * Cc + c);
}

// ---------------------------------------------------------------------------
// Kernel 2: paired alpha recursion + fused reduction. grid=B, 128 threads.
// ---------------------------------------------------------------------------
__global__ __launch_bounds__(NTHR, 1)
void ctc_alpha(const int* __restrict__ targets,
               const int* __restrict__ ilen,
               const int* __restrict__ tlen,
               float* __restrict__ out)
{
    // slot i+2 = thread i's (be,se,bo,so); slots 0,1 = permanent dead pads.
    __shared__ float4 sh[2][NTHR + 2];
    __shared__ int s_lastflag;

    const int b = blockIdx.x;
    const int i = threadIdx.x;
    const int last = ilen[b] - 1;    // >= 599 for this problem

    const int tgR   = (i < Ll)              ? targets[b * Ll + i]     : 0;
    const int tgpR  = (i >= 1 && i <= Ll)   ? targets[b * Ll + i - 1] : -1;
    const int tgppR = (i >= 2 && i <= Ll+1) ? targets[b * Ll + i - 2] : -1;
    const bool skip  = (tgR  != tgpR);   // own odd state's skip arc
    const bool skipP = (tgpR != tgppR);  // neighbor's odd state's skip arc
    // Emission columns within an emit row (clamped to 0=blank for pad lanes).
    const int jo = (i < Ll)            ? i + 1 : 0;   // own odd
    const int jp = (i >= 1 && i <= Ll) ? i     : 0;   // neighbor odd

    const float* __restrict__ em = g_emit + (size_t)b * Tt * EP;

    if (i < 2) {
        sh[0][i] = make_float4(NEGV, 0.f, NEGV, 0.f);
        sh[1][i] = make_float4(NEGV, 0.f, NEGV, 0.f);
    }

    // t=0 init (log2 domain, alpha = base + lg2(sum)); emit is pre-scaled.
    float se = 1.f, so = 1.f;
    float be = (i == 0) ? em[0]  : NEGV;
    float bo = (i == 0) ? em[jo] : NEGV;

    int buf = 0;
    sh[buf][i + 2] = make_float4(be, se, bo, so);
    __syncthreads();

    // One PAIR of steps (tc+1, tc+2); emissions already in log2 domain.
#define PAIR_BODY(e1b, e1o, e1p, e2b, e2o)                                   \
    {                                                                        \
        float4 n1 = sh[buf][i + 1];                                          \
        float4 n2 = sh[buf][i];                                              \
        /* redundant: neighbor (i-1)'s odd state at tc+1 */                  \
        float mR1, sR1; LAE(n1.z, n1.w, n1.x, n1.y, mR1, sR1);               \
        float bzR = skipP ? n2.z : NEGV, wzR = skipP ? n2.w : 0.f;           \
        float mRP, sP;  LAE(mR1, sR1, bzR, wzR, mRP, sP);                    \
        float bP = __fadd_rn(mRP, (e1p));                                    \
        /* own step tc+1 */                                                  \
        float mA, sA; LAE(be, se, n1.z, n1.w, mA, sA);                       \
        float m1, s1; LAE(bo, so, be, se, m1, s1);                           \
        float bzB = skip ? n1.z : NEGV, wzB = skip ? n1.w : 0.f;             \
        float mC, sC; LAE(m1, s1, bzB, wzB, mC, sC);                         \
        float be1 = __fadd_rn(mA, (e1b)), se1 = sA;                          \
        float bo1 = __fadd_rn(mC, (e1o)), so1 = sC;                          \
        /* own step tc+2 (neighbor odd = redundant (bP,sP)) */               \
        float mD, sD; LAE(be1, se1, bP, sP, mD, sD);                         \
        float mE, sE; LAE(bo1, so1, be1, se1, mE, sE);                       \
        float bzF = skip ? bP : NEGV, wzF = skip ? sP : 0.f;                 \
        float mF, sF; LAE(mE, sE, bzF, wzF, mF, sF);                         \
        be = __fadd_rn(mD, (e2b)); se = sD;                                  \
        bo = __fadd_rn(mF, (e2o)); so = sF;                                  \
    }

    // If step count (last) is odd, do ONE plain step so pairs align.
    int ts = 0;
    if (last & 1) {
        float4 n1 = sh[buf][i + 1];
        const float* p = em + EP;            // t = 1
        float e_b = p[0];
        float e_o = __ldg(p + jo);
        float mA, sA; LAE(be, se, n1.z, n1.w, mA, sA);
        float m1, s1; LAE(bo, so, be, se, m1, s1);
        float bz = skip ? n1.z : NEGV, wz = skip ? n1.w : 0.f;
        float mC, sC; LAE(m1, s1, bz, wz, mC, sC);
        be = __fadd_rn(mA, e_b); se = sA;
        bo = __fadd_rn(mC, e_o); so = sC;
        ts = 1;
        buf ^= 1;
        sh[buf][i + 2] = make_float4(be, se, bo, so);
        __syncthreads();
    }
    const int npairs = (last - ts) >> 1;          // >= 299 here
    const int nmain  = npairs & ~(DP - 1);        // grouped-unrolled portion

    // Register prefetch rings (indices are LITERALS everywhere below).
    float r1b[DP], r1o[DP], r1p[DP], r2b[DP], r2o[DP];
#pragma unroll
    for (int k = 0; k < DP; ++k) {
        const float* p1 = em + (size_t)(ts + 2 * k + 1) * EP;
        r1b[k] = p1[0]; r1o[k] = __ldg(p1 + jo); r1p[k] = __ldg(p1 + jp);
        r2b[k] = p1[EP]; r2o[k] = __ldg(p1 + EP + jo);
    }

    for (int pg = 0; pg < nmain; pg += DP) {
#pragma unroll
        for (int k = 0; k < DP; ++k) {            // k is a literal
            const int p = pg + k;
            const float e1b = r1b[k], e1o = r1o[k], e1p = r1p[k];
            const float e2b = r2b[k], e2o = r2o[k];
            int q = p + DP; if (q >= npairs) q = npairs - 1;
            const float* pp1 = em + (size_t)(ts + 2 * q + 1) * EP;
            r1b[k] = pp1[0]; r1o[k] = __ldg(pp1 + jo); r1p[k] = __ldg(pp1 + jp);
            r2b[k] = pp1[EP]; r2o[k] = __ldg(pp1 + EP + jo);

            PAIR_BODY(e1b, e1o, e1p, e2b, e2o);

            if ((p & 15) == 15) {    // fold every 32 steps (3^32 < f32max)
                be = fmaxf(be + lg2f(se), NEGV); se = 1.f;
                bo = fmaxf(bo + lg2f(so), NEGV); so = 1.f;
            }
            buf ^= 1;
            sh[buf][i + 2] = make_float4(be, se, bo, so);
            __syncthreads();
        }
    }

    // Remainder pairs (<=3): ring-free, direct loads.
    for (int p = nmain; p < npairs; ++p) {
        const float* p1 = em + (size_t)(ts + 2 * p + 1) * EP;
        float e1b = p1[0], e1o = __ldg(p1 + jo), e1p = __ldg(p1 + jp);
        float e2b = p1[EP], e2o = __ldg(p1 + EP + jo);
        PAIR_BODY(e1b, e1o, e1p, e2b, e2o);
        buf ^= 1;
        sh[buf][i + 2] = make_float4(be, se, bo, so);
        __syncthreads();
    }

    // Final fold + publish (sum folded to 1 so .x/.z are full alphas).
    be = fmaxf(be + lg2f(se), NEGV);
    bo = fmaxf(bo + lg2f(so), NEGV);
    buf ^= 1;
    sh[buf][i + 2] = make_float4(be, 1.f, bo, 1.f);
    __syncthreads();

    if (i == 0) {
        int Lb = tlen[b];
        float x = sh[buf][Lb + 2].x;     // even state 2Lb   (thread Lb)
        float y = sh[buf][Lb + 1].z;     // odd  state 2Lb-1 (thread Lb-1)
        float m = fmaxf(x, y);
        g_tot[b] = LN2 * (m + lg2f(ex2f(x - m) + ex2f(y - m)));
        __threadfence();
        unsigned v = atomicAdd(&g_done, 1u);
        s_lastflag = (v == Bb - 1u) ? 1 : 0;
    }
    __syncthreads();

    if (s_lastflag && i < 32) {          // last block: fused reduction
        __threadfence();
        float tot = g_tot[i];
        float il  = (float)ilen[i];
        bool  ok  = tot > NEGV * 0.5f;
        float tsum = ok ? tot : 0.f;
        float tf   = ok ? il  : 0.f;
        float af   = il;
#pragma unroll
        for (int s = 16; s >= 1; s >>= 1) {
            tsum += __shfl_down_sync(0xFFFFFFFFu, tsum, s);
            tf   += __shfl_down_sync(0xFFFFFFFFu, tf, s);
            af   += __shfl_down_sync(0xFFFFFFFFu, af, s);
        }
        if (i == 0) {
            out[0] = tsum; out[1] = tf; out[2] = af;
            g_done = 0;                  // reset for next graph replay
        }
    }
}

// ---------------------------------------------------------------------------
extern "C" void kernel_launch(void* const* d_in, const int* in_sizes, int n_in,
                              void* d_out, int out_size) {
    const float* lp      = (const float*)d_in[0];  // nnet_output [B,T,C] f32
    const int*   targets = (const int*)  d_in[1];  // [B,L] i32
    const int*   ilen    = (const int*)  d_in[2];  // [B] i32
    const int*   tlen    = (const int*)  d_in[3];  // [B] i32

    const int total = Bb * Tt * (Ll + 1);
    gather_kernel<<<(total + 255) / 256, 256>>>(lp, targets, ilen);
    ctc_alpha<<<Bb, NTHR>>>(targets, ilen, tlen, (float*)d_out);
}